// round 1
// baseline (speedup 1.0000x reference)
#include <cuda_runtime.h>
#include <math.h>

#define TT    1024
#define BB    64
#define HH    512
#define HIDD  512
#define NG    2048           // 4*HID
#define NROWS 65536          // T*B

// ------------------------- scratch (static device memory; no allocs) -------------------------
static __device__ float d_Y  [(size_t)NROWS * HH];     // normalized input          128MB
static __device__ float d_Yr [(size_t)NROWS * HH];     // flipped normalized input  128MB
static __device__ float d_Zf [(size_t)NROWS * NG];     // Y  @ Wx_f + b_f           512MB
static __device__ float d_Zb [(size_t)NROWS * NG];     // Yr @ Wx_b + b_b           512MB
static __device__ float d_bwd[(size_t)NROWS * HIDD];   // raw backward states       128MB
static __device__ float d_Wxr[2][HH  * NG];            // gate-interleaved Wx
static __device__ float d_Whr[2][HIDD* NG];            // gate-interleaved Wh
static __device__ float d_brd[2][NG];                  // gate-interleaved bias
static __device__ float d_hT [2][2][HIDD * BB];        // double-buffered h^T [hid][batch]
static __device__ float d_sum[HH];
static __device__ float d_sumsq[HH];
static __device__ float d_an[HH];                      // scale * invstd
static __device__ float d_b2[HH];                      // bias - mean*scale*invstd
static __device__ unsigned d_bar;                      // grid barrier counter

__device__ __forceinline__ float sigm(float x) { return 1.0f / (1.0f + __expf(-x)); }

// ------------------------- init: zero stats, h buffers, barrier -------------------------
__global__ void k_init() {
    int i = blockIdx.x * blockDim.x + threadIdx.x;
    if (i < 2 * 2 * HIDD * BB) ((float*)d_hT)[i] = 0.0f;
    if (i < HH) { d_sum[i] = 0.0f; d_sumsq[i] = 0.0f; }
    if (i == 0) d_bar = 0u;
}

// ------------------------- batchnorm column sums -------------------------
__global__ void k_stats(const float* __restrict__ x) {
    int c = threadIdx.x;                       // 512 threads = 512 columns
    size_t r0 = (size_t)blockIdx.x * 256;
    float s = 0.0f, s2 = 0.0f;
    for (int r = 0; r < 256; r++) {
        float v = x[(r0 + r) * (size_t)HH + c];
        s += v; s2 += v * v;
    }
    atomicAdd(&d_sum[c], s);
    atomicAdd(&d_sumsq[c], s2);
}

// ------------------------- finalize BN affine params -------------------------
__global__ void k_finalize(const int* __restrict__ lengths, const float* __restrict__ scale,
                           const float* __restrict__ bias, const int* __restrict__ training) {
    __shared__ float s_nz;
    int tid = threadIdx.x;                      // 512 threads
    if (tid == 0) {
        int s = 0;
        for (int b = 0; b < BB; b++) s += lengths[b];
        s_nz = (float)s;
    }
    __syncthreads();
    float mean, var;
    if (*training) {
        float nz = s_nz;
        mean = d_sum[tid] / nz;
        float m2 = d_sumsq[tid] / nz;
        var = fmaxf(0.0f, m2 - mean * mean);
    } else {
        mean = 0.0f; var = 1.0f;
    }
    float a = rsqrtf(var + 1e-5f) * scale[tid];
    d_an[tid] = a;
    d_b2[tid] = bias[tid] - mean * a;
}

// ------------------------- gate-interleave reorder: col' = j*4+g <- g*512+j -------------------------
__global__ void k_reorder(const float* __restrict__ Wxf, const float* __restrict__ Whf,
                          const float* __restrict__ Wxb, const float* __restrict__ Whb,
                          const float* __restrict__ bf,  const float* __restrict__ bb) {
    int z = blockIdx.z;
    int i = blockIdx.x * 256 + threadIdx.x;     // < 512*2048
    const float* src = (z == 0) ? Wxf : (z == 1) ? Whf : (z == 2) ? Wxb : Whb;
    float* dst = (z == 0) ? d_Wxr[0] : (z == 1) ? d_Whr[0] : (z == 2) ? d_Wxr[1] : d_Whr[1];
    int k = i >> 11, cn = i & 2047;
    int g = cn & 3, j = cn >> 2;
    dst[i] = src[(k << 11) + (g << 9) + j];
    if (i < NG) {
        if (z == 0)      d_brd[0][i] = bf[((i & 3) << 9) + (i >> 2)];
        else if (z == 2) d_brd[1][i] = bb[((i & 3) << 9) + (i >> 2)];
    }
}

// ------------------------- apply BN + mask, write Y and flipped Yr -------------------------
__global__ void k_bnapply(const float* __restrict__ x, const float* __restrict__ mask,
                          const int* __restrict__ lengths) {
    int i = blockIdx.x * 256 + threadIdx.x;     // float4 index over 65536*128
    int row = i >> 7;
    int c4  = (i & 127) << 2;
    int t = row >> 6, b = row & 63;
    float4 xv = *(const float4*)(x + ((size_t)row << 9) + c4);
    float4 av = *(const float4*)(d_an + c4);
    float4 bv = *(const float4*)(d_b2 + c4);
    float m = __ldg(mask + row);
    float4 y;
    y.x = (xv.x * av.x + bv.x) * m;
    y.y = (xv.y * av.y + bv.y) * m;
    y.z = (xv.z * av.z + bv.z) * m;
    y.w = (xv.w * av.w + bv.w) * m;
    *(float4*)(d_Y + ((size_t)row << 9) + c4) = y;
    int l = __ldg(lengths + b);
    if (t < l) {
        int rr = (l - 1 - t) * BB + b;
        *(float4*)(d_Yr + ((size_t)rr << 9) + c4) = y;
    } else {
        *(float4*)(d_Yr + ((size_t)row << 9) + c4) = make_float4(0.f, 0.f, 0.f, 0.f);
    }
}

// ------------------------- big input GEMM: Z = Y @ Wxr + br  (128x128x8 tiles) -------------------------
__global__ __launch_bounds__(256) void k_sgemm() {
    int dir = blockIdx.z;
    const float* __restrict__ A    = dir ? d_Yr : d_Y;
    const float* __restrict__ Bm   = d_Wxr[dir];
    const float* __restrict__ bias = d_brd[dir];
    float* __restrict__ C          = dir ? d_Zb : d_Zf;

    __shared__ __align__(16) float As[8][128];
    __shared__ __align__(16) float Bs[8][128];
    int tid = threadIdx.x;
    int bx = blockIdx.x, by = blockIdx.y;
    int arow = tid >> 1,  acol = (tid & 1) << 2;
    int brow = tid >> 5,  bcol = (tid & 31) << 2;
    int tx = tid & 15,    ty = tid >> 4;

    const float* Ap = A + ((size_t)(by * 128 + arow)) * HH + acol;
    const float* Bp = Bm + (size_t)brow * NG + bx * 128 + bcol;

    float acc[8][8];
#pragma unroll
    for (int i = 0; i < 8; i++)
#pragma unroll
        for (int j = 0; j < 8; j++) acc[i][j] = 0.0f;

    for (int k0 = 0; k0 < HH; k0 += 8) {
        float4 a4 = *(const float4*)(Ap + k0);
        float4 b4 = *(const float4*)(Bp + (size_t)k0 * NG);
        As[acol + 0][arow] = a4.x;
        As[acol + 1][arow] = a4.y;
        As[acol + 2][arow] = a4.z;
        As[acol + 3][arow] = a4.w;
        *(float4*)&Bs[brow][bcol] = b4;
        __syncthreads();
#pragma unroll
        for (int kk = 0; kk < 8; kk++) {
            float av[8], bv[8];
            *(float4*)&av[0] = *(const float4*)&As[kk][ty * 8];
            *(float4*)&av[4] = *(const float4*)&As[kk][ty * 8 + 4];
            *(float4*)&bv[0] = *(const float4*)&Bs[kk][tx * 8];
            *(float4*)&bv[4] = *(const float4*)&Bs[kk][tx * 8 + 4];
#pragma unroll
            for (int i = 0; i < 8; i++)
#pragma unroll
                for (int j = 0; j < 8; j++) acc[i][j] = fmaf(av[i], bv[j], acc[i][j]);
        }
        __syncthreads();
    }
#pragma unroll
    for (int i = 0; i < 8; i++) {
        size_t row = (size_t)by * 128 + ty * 8 + i;
        float* Cp = C + row * NG + bx * 128 + tx * 8;
#pragma unroll
        for (int j = 0; j < 8; j += 4) {
            float4 v;
            v.x = acc[i][j + 0] + bias[bx * 128 + tx * 8 + j + 0];
            v.y = acc[i][j + 1] + bias[bx * 128 + tx * 8 + j + 1];
            v.z = acc[i][j + 2] + bias[bx * 128 + tx * 8 + j + 2];
            v.w = acc[i][j + 3] + bias[bx * 128 + tx * 8 + j + 3];
            *(float4*)(Cp + j) = v;
        }
    }
}

// ------------------------- persistent bidirectional LSTM recurrence -------------------------
// grid 128 blocks (64 fwd, 64 bwd), 128 threads. Block n handles hids n*8..n*8+7 (32 reordered
// z-cols). Thread: 4 batch rows x 1 hid (its 4 gates). c-state in registers across all steps.
__global__ __launch_bounds__(128) void k_lstm(float* __restrict__ out) {
    int blk = blockIdx.x;
    int dir = blk >> 6;
    int n   = blk & 63;
    const float* __restrict__ Zx = dir ? d_Zb : d_Zf;
    const float* __restrict__ Wh = d_Whr[dir];
    float* __restrict__ hob = dir ? d_bwd : out;
    float* hbuf0 = d_hT[dir][0];
    float* hbuf1 = d_hT[dir][1];

    int tid = threadIdx.x;
    int tx = tid & 7;        // local hid
    int ty = tid >> 3;       // row group (rows ty*4..ty*4+3)
    int j = n * 8 + tx;
    int col4 = j << 2;

    __shared__ __align__(16) float hs[64 * BB];   // h^T chunk [64 k][64 rows]  16KB
    __shared__ __align__(16) float ws[64 * 32];   // Wh  chunk [64 k][32 cols]   8KB

    float c[4] = {0.f, 0.f, 0.f, 0.f};

    for (int t = 0; t < TT; t++) {
        const float* hcur = (t & 1) ? hbuf1 : hbuf0;
        float*       hnxt = (t & 1) ? hbuf0 : hbuf1;

        float acc[4][4];
#pragma unroll
        for (int r = 0; r < 4; r++) {
            float4 z = *(const float4*)(Zx + ((size_t)(t * BB + ty * 4 + r)) * NG + col4);
            acc[r][0] = z.x; acc[r][1] = z.y; acc[r][2] = z.z; acc[r][3] = z.w;
        }

        for (int k0 = 0; k0 < HIDD; k0 += 64) {
            // stage h^T chunk (L2-coherent loads: written by other SMs last step)
#pragma unroll
            for (int i = 0; i < 8; i++) {
                int q = tid + i * 128;
                ((float4*)hs)[q] = __ldcg((const float4*)(hcur + k0 * BB) + q);
            }
            // stage Wh chunk
#pragma unroll
            for (int i = 0; i < 4; i++) {
                int q = tid + i * 128;
                int kk = q >> 3, cc = (q & 7) << 2;
                ((float4*)ws)[q] = *(const float4*)(Wh + (size_t)(k0 + kk) * NG + n * 32 + cc);
            }
            __syncthreads();
#pragma unroll 8
            for (int kk = 0; kk < 64; kk++) {
                float4 h4 = *(const float4*)(hs + kk * BB + ty * 4);
                float4 w4 = *(const float4*)(ws + kk * 32 + tx * 4);
                float hv[4] = {h4.x, h4.y, h4.z, h4.w};
                float wv[4] = {w4.x, w4.y, w4.z, w4.w};
#pragma unroll
                for (int r = 0; r < 4; r++)
#pragma unroll
                    for (int g = 0; g < 4; g++)
                        acc[r][g] = fmaf(hv[r], wv[g], acc[r][g]);
            }
            __syncthreads();
        }

        // gates: reordered cols are (i,f,g,o)
        float hn[4];
#pragma unroll
        for (int r = 0; r < 4; r++) {
            float zi = acc[r][0], zf = acc[r][1], zg = acc[r][2], zo = acc[r][3];
            float cn = sigm(zf) * c[r] + sigm(zi) * tanhf(zg);
            c[r] = cn;
            hn[r] = sigm(zo) * tanhf(cn);
        }

        // publish h for next step (transposed layout: [hid][batch])
        *(float4*)(hnxt + j * BB + ty * 4) = make_float4(hn[0], hn[1], hn[2], hn[3]);
        // write output states
#pragma unroll
        for (int r = 0; r < 4; r++)
            hob[((size_t)(t * BB + ty * 4 + r)) * HIDD + j] = hn[r];

        // grid barrier
        __threadfence();
        __syncthreads();
        if (tid == 0) {
            atomicAdd(&d_bar, 1u);
            unsigned target = (unsigned)(t + 1) * gridDim.x;
            volatile unsigned* vb = &d_bar;
            while (*vb < target) { }
            __threadfence();
        }
        __syncthreads();
    }
}

// ------------------------- combine: out += flip(bwd) -------------------------
__global__ void k_combine(float* __restrict__ out, const int* __restrict__ lengths) {
    int i = blockIdx.x * 256 + threadIdx.x;    // float4 index
    int row = i >> 7;
    int c4  = (i & 127) << 2;
    int t = row >> 6, b = row & 63;
    int l = __ldg(lengths + b);
    int src = (t < l) ? (l - 1 - t) : (TT - 1 - t + l);
    float4 v = *(const float4*)(d_bwd + ((size_t)(src * BB + b) << 9) + c4);
    float4* po = (float4*)(out + ((size_t)row << 9) + c4);
    float4 o = *po;
    o.x += v.x; o.y += v.y; o.z += v.z; o.w += v.w;
    *po = o;
}

// ------------------------- launch -------------------------
extern "C" void kernel_launch(void* const* d_in, const int* in_sizes, int n_in,
                              void* d_out, int out_size) {
    const float* x        = (const float*)d_in[0];
    const int*   lengths  = (const int*)  d_in[1];
    const float* mask     = (const float*)d_in[2];
    const float* scale    = (const float*)d_in[3];
    const float* bias     = (const float*)d_in[4];
    const float* Wxf      = (const float*)d_in[5];
    const float* Whf      = (const float*)d_in[6];
    const float* bf       = (const float*)d_in[7];
    const float* Wxb      = (const float*)d_in[8];
    const float* Whb      = (const float*)d_in[9];
    const float* bb       = (const float*)d_in[10];
    const int*   training = (const int*)  d_in[11];
    float* out = (float*)d_out;

    k_init<<<512, 256>>>();
    k_stats<<<256, 512>>>(x);
    k_finalize<<<1, 512>>>(lengths, scale, bias, training);
    k_reorder<<<dim3(4096, 1, 4), 256>>>(Wxf, Whf, Wxb, Whb, bf, bb);
    k_bnapply<<<32768, 256>>>(x, mask, lengths);
    k_sgemm<<<dim3(16, 512, 2), 256>>>();
    k_lstm<<<128, 128>>>(out);
    k_combine<<<32768, 256>>>(out, lengths);
}

// round 4
// speedup vs baseline: 1.0276x; 1.0276x over previous
#include <cuda_runtime.h>
#include <cuda_bf16.h>
#include <cstdint>
#include <math.h>

#define TT    1024
#define BB    64
#define HH    512
#define HIDD  512
#define NG    2048           // 4*HID
#define NROWS 65536          // T*B

// ------------------------- scratch (static device memory; no allocs) -------------------------
static __device__ float d_Zf [(size_t)NROWS * NG];     // Y  @ Wx_f + b_f           512MB
static __device__ float d_Zb [(size_t)NROWS * NG];     // Yr @ Wx_b + b_b           512MB
static __device__ float d_bwd[(size_t)NROWS * HIDD];   // raw backward states       128MB
static __device__ unsigned short d_Yh [(size_t)NROWS * HH];   // bf16 hi of Y
static __device__ unsigned short d_Yl [(size_t)NROWS * HH];   // bf16 lo of Y
static __device__ unsigned short d_Yrh[(size_t)NROWS * HH];   // flipped hi
static __device__ unsigned short d_Yrl[(size_t)NROWS * HH];   // flipped lo
static __device__ unsigned short d_Wxh[2][NG * HH];    // Wx bf16 hi, [n'][k] gate-interleaved
static __device__ unsigned short d_Wxl[2][NG * HH];    // Wx bf16 lo
static __device__ float d_Whr[2][HIDD * NG];           // gate-interleaved Wh (fp32)
static __device__ float d_brd[2][NG];                  // gate-interleaved bias
static __device__ float d_hT [2][2][HIDD * BB];        // double-buffered h^T [hid][batch]
static __device__ float d_sum[HH];
static __device__ float d_sumsq[HH];
static __device__ float d_an[HH];
static __device__ float d_b2[HH];
static __device__ unsigned d_bar;

__device__ __forceinline__ float sigm(float x) { return 1.0f / (1.0f + __expf(-x)); }

__device__ __forceinline__ uint32_t smem_u32(const void* p) {
    uint32_t a;
    asm("{ .reg .u64 t; cvta.to.shared.u64 t, %1; cvt.u32.u64 %0, t; }" : "=r"(a) : "l"(p));
    return a;
}

__device__ __forceinline__ void cpa16(uint32_t dst, const void* src) {
    asm volatile("cp.async.cg.shared.global [%0], [%1], 16;" :: "r"(dst), "l"(src));
}
#define CPA_COMMIT() asm volatile("cp.async.commit_group;" ::: "memory")
#define CPA_WAIT1()  asm volatile("cp.async.wait_group 1;" ::: "memory")
#define CPA_WAIT0()  asm volatile("cp.async.wait_group 0;" ::: "memory")

__device__ __forceinline__ void ldsm4(uint32_t* d, uint32_t a) {
    asm volatile("ldmatrix.sync.aligned.m8n8.x4.shared.b16 {%0,%1,%2,%3}, [%4];"
                 : "=r"(d[0]), "=r"(d[1]), "=r"(d[2]), "=r"(d[3]) : "r"(a));
}
__device__ __forceinline__ void ldsm2(uint32_t* d, uint32_t a) {
    asm volatile("ldmatrix.sync.aligned.m8n8.x2.shared.b16 {%0,%1}, [%2];"
                 : "=r"(d[0]), "=r"(d[1]) : "r"(a));
}
__device__ __forceinline__ void mma16816(float* d, const uint32_t* a, const uint32_t* b) {
    asm volatile("mma.sync.aligned.m16n8k16.row.col.f32.bf16.bf16.f32 "
                 "{%0,%1,%2,%3}, {%4,%5,%6,%7}, {%8,%9}, {%0,%1,%2,%3};"
                 : "+f"(d[0]), "+f"(d[1]), "+f"(d[2]), "+f"(d[3])
                 : "r"(a[0]), "r"(a[1]), "r"(a[2]), "r"(a[3]), "r"(b[0]), "r"(b[1]));
}

// ------------------------- init -------------------------
__global__ void k_init() {
    int i = blockIdx.x * blockDim.x + threadIdx.x;
    if (i < 2 * 2 * HIDD * BB) ((float*)d_hT)[i] = 0.0f;
    if (i < HH) { d_sum[i] = 0.0f; d_sumsq[i] = 0.0f; }
    if (i == 0) d_bar = 0u;
}

// ------------------------- batchnorm column sums -------------------------
__global__ void k_stats(const float* __restrict__ x) {
    int c = threadIdx.x;
    size_t r0 = (size_t)blockIdx.x * 256;
    float s = 0.0f, s2 = 0.0f;
    for (int r = 0; r < 256; r++) {
        float v = x[(r0 + r) * (size_t)HH + c];
        s += v; s2 += v * v;
    }
    atomicAdd(&d_sum[c], s);
    atomicAdd(&d_sumsq[c], s2);
}

// ------------------------- finalize BN params -------------------------
__global__ void k_finalize(const int* __restrict__ lengths, const float* __restrict__ scale,
                           const float* __restrict__ bias, const int* __restrict__ training) {
    __shared__ float s_nz;
    int tid = threadIdx.x;
    if (tid == 0) {
        int s = 0;
        for (int b = 0; b < BB; b++) s += lengths[b];
        s_nz = (float)s;
    }
    __syncthreads();
    float mean, var;
    if (*training) {
        float nz = s_nz;
        mean = d_sum[tid] / nz;
        float m2 = d_sumsq[tid] / nz;
        var = fmaxf(0.0f, m2 - mean * mean);
    } else {
        mean = 0.0f; var = 1.0f;
    }
    float a = rsqrtf(var + 1e-5f) * scale[tid];
    d_an[tid] = a;
    d_b2[tid] = bias[tid] - mean * a;
}

// ------------------------- weight reorder -------------------------
// Wh: fp32 [k][n'] gate-interleaved (n' = j*4+g). Wx: bf16 hi/lo [n'][k].
__global__ void k_reorder(const float* __restrict__ Wxf, const float* __restrict__ Whf,
                          const float* __restrict__ Wxb, const float* __restrict__ Whb,
                          const float* __restrict__ bf,  const float* __restrict__ bb) {
    int z = blockIdx.z;
    int i = blockIdx.x * 256 + threadIdx.x;    // < 512*2048
    const float* src = (z == 0) ? Wxf : (z == 1) ? Whf : (z == 2) ? Wxb : Whb;
    if (z == 1 || z == 3) {
        int dir = z >> 1;
        int k = i >> 11, cn = i & 2047;
        int g = cn & 3, j = cn >> 2;
        d_Whr[dir][i] = src[(k << 11) + (g << 9) + j];
    } else {
        int dir = z >> 1;
        int k = i & 511, n = i >> 9;
        int g = n & 3, j = n >> 2;
        float v = src[(k << 11) + (g << 9) + j];
        __nv_bfloat16 h = __float2bfloat16_rn(v);
        float lo = v - __bfloat162float(h);
        d_Wxh[dir][i] = __bfloat16_as_ushort(h);
        d_Wxl[dir][i] = __bfloat16_as_ushort(__float2bfloat16_rn(lo));
        if (i < NG) {
            if (z == 0)      d_brd[0][i] = bf[((i & 3) << 9) + (i >> 2)];
            else             d_brd[1][i] = bb[((i & 3) << 9) + (i >> 2)];
        }
    }
}

// ------------------------- BN apply + mask + bf16 split + flip -------------------------
__global__ void k_bnapply(const float* __restrict__ x, const float* __restrict__ mask,
                          const int* __restrict__ lengths) {
    int i = blockIdx.x * 256 + threadIdx.x;     // float4 index over 65536*128
    int row = i >> 7;
    int c4  = (i & 127) << 2;
    int t = row >> 6, b = row & 63;
    float4 xv = *(const float4*)(x + ((size_t)row << 9) + c4);
    float4 av = *(const float4*)(d_an + c4);
    float4 bv = *(const float4*)(d_b2 + c4);
    float m = __ldg(mask + row);
    float y[4];
    y[0] = (xv.x * av.x + bv.x) * m;
    y[1] = (xv.y * av.y + bv.y) * m;
    y[2] = (xv.z * av.z + bv.z) * m;
    y[3] = (xv.w * av.w + bv.w) * m;
    uint2 hv, lv;
    unsigned hs[4], ls[4];
#pragma unroll
    for (int q = 0; q < 4; q++) {
        __nv_bfloat16 h = __float2bfloat16_rn(y[q]);
        float lo = y[q] - __bfloat162float(h);
        hs[q] = __bfloat16_as_ushort(h);
        ls[q] = __bfloat16_as_ushort(__float2bfloat16_rn(lo));
    }
    hv.x = hs[0] | (hs[1] << 16); hv.y = hs[2] | (hs[3] << 16);
    lv.x = ls[0] | (ls[1] << 16); lv.y = ls[2] | (ls[3] << 16);
    size_t o = ((size_t)row << 9) + c4;
    *(uint2*)(d_Yh + o) = hv;
    *(uint2*)(d_Yl + o) = lv;
    int l = __ldg(lengths + b);
    if (t < l) {
        size_t orr = ((size_t)((l - 1 - t) * BB + b) << 9) + c4;
        *(uint2*)(d_Yrh + orr) = hv;
        *(uint2*)(d_Yrl + orr) = lv;
    } else {
        *(uint2*)(d_Yrh + o) = make_uint2(0u, 0u);
        *(uint2*)(d_Yrl + o) = make_uint2(0u, 0u);
    }
}

// ------------------------- HMMA split-bf16 GEMM: Z = Y@Wx + b -------------------------
// block 128x128, 8 warps (2M x 4N), warp tile 64x32, K chunks of 32, double-buffered.
// smem rows are 128B (chunks 0-3 = hi k0..31, chunks 4-7 = lo), XOR-swizzled.
#define STAGE 32768
__global__ __launch_bounds__(256) void k_hgemm() {
    extern __shared__ char dsm[];
    uint32_t sb = (smem_u32(dsm) + 127) & ~127u;
    int tid = threadIdx.x;
    int lane = tid & 31, wid = tid >> 5;
    int wm0 = (wid & 1) * 64;
    int wn0 = (wid >> 1) * 32;
    int n0 = blockIdx.x * 128;       // n fastest -> weight tiles stay L2 resident
    int m0 = blockIdx.y * 128;
    int dir = blockIdx.z;

    const unsigned short* Ah = (dir ? d_Yrh : d_Yh) + (size_t)m0 * 512;
    const unsigned short* Al = (dir ? d_Yrl : d_Yl) + (size_t)m0 * 512;
    const unsigned short* Bh = d_Wxh[dir] + (size_t)n0 * 512;
    const unsigned short* Bl = d_Wxl[dir] + (size_t)n0 * 512;

    float acc[4][4][4];
#pragma unroll
    for (int a = 0; a < 4; a++)
#pragma unroll
        for (int b = 0; b < 4; b++)
#pragma unroll
            for (int c = 0; c < 4; c++) acc[a][b][c] = 0.0f;

    auto load_chunk = [&](int s, int k0) {
        uint32_t bA = sb + s * STAGE, bB = bA + 16384;
#pragma unroll
        for (int it = 0; it < 4; it++) {
            int q = tid + it * 256;            // 0..1023
            int r = q >> 3, c = q & 7;
            uint32_t sw = (uint32_t)r * 128 + (uint32_t)((c ^ (r & 7)) << 4);
            cpa16(bA + sw, (c < 4) ? (const void*)(Ah + (size_t)r * 512 + k0 + c * 8)
                                   : (const void*)(Al + (size_t)r * 512 + k0 + (c - 4) * 8));
            cpa16(bB + sw, (c < 4) ? (const void*)(Bh + (size_t)r * 512 + k0 + c * 8)
                                   : (const void*)(Bl + (size_t)r * 512 + k0 + (c - 4) * 8));
        }
    };

    load_chunk(0, 0);  CPA_COMMIT();
    load_chunk(1, 32); CPA_COMMIT();

    for (int i = 0; i < 16; i++) {
        if (i < 15) CPA_WAIT1(); else CPA_WAIT0();
        __syncthreads();
        uint32_t bA = sb + (i & 1) * STAGE, bB = bA + 16384;
#pragma unroll
        for (int ks = 0; ks < 2; ks++) {
            uint32_t ah[4][4], al[4][4];
#pragma unroll
            for (int mf = 0; mf < 4; mf++) {
                int r = wm0 + mf * 16 + (lane & 15);
                int ch = 2 * ks + (lane >> 4);
                ldsm4(ah[mf], bA + r * 128 + ((ch       ^ (r & 7)) << 4));
                ldsm4(al[mf], bA + r * 128 + (((ch + 4) ^ (r & 7)) << 4));
            }
#pragma unroll
            for (int nf = 0; nf < 4; nf++) {
                int rb = wn0 + nf * 8 + (lane & 7);
                int cb = 2 * ks + ((lane >> 3) & 1);
                uint32_t bh[2], bl[2];
                ldsm2(bh, bB + rb * 128 + ((cb       ^ (rb & 7)) << 4));
                ldsm2(bl, bB + rb * 128 + (((cb + 4) ^ (rb & 7)) << 4));
#pragma unroll
                for (int mf = 0; mf < 4; mf++) {
                    mma16816(acc[mf][nf], ah[mf], bh);
                    mma16816(acc[mf][nf], ah[mf], bl);
                    mma16816(acc[mf][nf], al[mf], bh);
                }
            }
        }
        __syncthreads();
        if (i + 2 < 16) { load_chunk(i & 1, (i + 2) * 32); CPA_COMMIT(); }
    }

    // epilogue: direct STG.64 with fused bias
    const float* bias = d_brd[dir];
    float* Z = dir ? d_Zb : d_Zf;
#pragma unroll
    for (int nf = 0; nf < 4; nf++) {
        int gn = n0 + wn0 + nf * 8 + (lane & 3) * 2;
        float b0 = __ldg(bias + gn), b1 = __ldg(bias + gn + 1);
#pragma unroll
        for (int mf = 0; mf < 4; mf++) {
            int gm = m0 + wm0 + mf * 16 + (lane >> 2);
            float2 v0 = make_float2(acc[mf][nf][0] + b0, acc[mf][nf][1] + b1);
            float2 v1 = make_float2(acc[mf][nf][2] + b0, acc[mf][nf][3] + b1);
            *(float2*)(Z + (size_t)gm * NG + gn) = v0;
            *(float2*)(Z + (size_t)(gm + 8) * NG + gn) = v1;
        }
    }
}

// ------------------------- persistent bidirectional LSTM recurrence (f32x2 inner) ----------
__global__ __launch_bounds__(128) void k_lstm(float* __restrict__ out) {
    int blk = blockIdx.x;
    int dir = blk >> 6;
    int n   = blk & 63;
    const float* __restrict__ Zx = dir ? d_Zb : d_Zf;
    const float* __restrict__ Wh = d_Whr[dir];
    float* __restrict__ hob = dir ? d_bwd : out;
    float* hbuf0 = d_hT[dir][0];
    float* hbuf1 = d_hT[dir][1];

    int tid = threadIdx.x;
    int tx = tid & 7;
    int ty = tid >> 3;
    int j = n * 8 + tx;
    int col4 = j << 2;

    __shared__ __align__(16) float hs[64 * BB];
    __shared__ __align__(16) float ws[64 * 32];

    float c[4] = {0.f, 0.f, 0.f, 0.f};

    for (int t = 0; t < TT; t++) {
        const float* hcur = (t & 1) ? hbuf1 : hbuf0;
        float*       hnxt = (t & 1) ? hbuf0 : hbuf1;

        unsigned long long acc2[4][2];
#pragma unroll
        for (int r = 0; r < 4; r++) {
            float4 z = *(const float4*)(Zx + ((size_t)(t * BB + ty * 4 + r)) * NG + col4);
            asm("mov.b64 %0, {%1,%2};" : "=l"(acc2[r][0])
                : "r"(__float_as_uint(z.x)), "r"(__float_as_uint(z.y)));
            asm("mov.b64 %0, {%1,%2};" : "=l"(acc2[r][1])
                : "r"(__float_as_uint(z.z)), "r"(__float_as_uint(z.w)));
        }

        for (int k0 = 0; k0 < HIDD; k0 += 64) {
#pragma unroll
            for (int i = 0; i < 8; i++) {
                int q = tid + i * 128;
                ((float4*)hs)[q] = __ldcg((const float4*)(hcur + k0 * BB) + q);
            }
#pragma unroll
            for (int i = 0; i < 4; i++) {
                int q = tid + i * 128;
                int kk = q >> 3, cc = (q & 7) << 2;
                ((float4*)ws)[q] = *(const float4*)(Wh + (size_t)(k0 + kk) * NG + n * 32 + cc);
            }
            __syncthreads();
#pragma unroll 8
            for (int kk = 0; kk < 64; kk++) {
                float4 h4 = *(const float4*)(hs + kk * BB + ty * 4);
                ulonglong2 w2 = *(const ulonglong2*)(ws + kk * 32 + tx * 4);
                float hv[4] = {h4.x, h4.y, h4.z, h4.w};
#pragma unroll
                for (int r = 0; r < 4; r++) {
                    unsigned long long hb;
                    asm("mov.b64 %0, {%1,%1};" : "=l"(hb) : "r"(__float_as_uint(hv[r])));
                    asm("fma.rn.f32x2 %0, %1, %2, %0;" : "+l"(acc2[r][0]) : "l"(hb), "l"(w2.x));
                    asm("fma.rn.f32x2 %0, %1, %2, %0;" : "+l"(acc2[r][1]) : "l"(hb), "l"(w2.y));
                }
            }
            __syncthreads();
        }

        float hn[4];
#pragma unroll
        for (int r = 0; r < 4; r++) {
            uint32_t u0, u1, u2, u3;
            asm("mov.b64 {%0,%1}, %2;" : "=r"(u0), "=r"(u1) : "l"(acc2[r][0]));
            asm("mov.b64 {%0,%1}, %2;" : "=r"(u2), "=r"(u3) : "l"(acc2[r][1]));
            float zi = __uint_as_float(u0), zf = __uint_as_float(u1);
            float zg = __uint_as_float(u2), zo = __uint_as_float(u3);
            float cn = sigm(zf) * c[r] + sigm(zi) * tanhf(zg);
            c[r] = cn;
            hn[r] = sigm(zo) * tanhf(cn);
        }

        *(float4*)(hnxt + j * BB + ty * 4) = make_float4(hn[0], hn[1], hn[2], hn[3]);
#pragma unroll
        for (int r = 0; r < 4; r++)
            hob[((size_t)(t * BB + ty * 4 + r)) * HIDD + j] = hn[r];

        __threadfence();
        __syncthreads();
        if (tid == 0) {
            atomicAdd(&d_bar, 1u);
            unsigned target = (unsigned)(t + 1) * gridDim.x;
            volatile unsigned* vb = &d_bar;
            while (*vb < target) { }
            __threadfence();
        }
        __syncthreads();
    }
}

// ------------------------- combine: out += flip(bwd) -------------------------
__global__ void k_combine(float* __restrict__ out, const int* __restrict__ lengths) {
    int i = blockIdx.x * 256 + threadIdx.x;
    int row = i >> 7;
    int c4  = (i & 127) << 2;
    int t = row >> 6, b = row & 63;
    int l = __ldg(lengths + b);
    int src = (t < l) ? (l - 1 - t) : (TT - 1 - t + l);
    float4 v = *(const float4*)(d_bwd + ((size_t)(src * BB + b) << 9) + c4);
    float4* po = (float4*)(out + ((size_t)row << 9) + c4);
    float4 o = *po;
    o.x += v.x; o.y += v.y; o.z += v.z; o.w += v.w;
    *po = o;
}

// ------------------------- launch -------------------------
extern "C" void kernel_launch(void* const* d_in, const int* in_sizes, int n_in,
                              void* d_out, int out_size) {
    const float* x        = (const float*)d_in[0];
    const int*   lengths  = (const int*)  d_in[1];
    const float* mask     = (const float*)d_in[2];
    const float* scale    = (const float*)d_in[3];
    const float* bias     = (const float*)d_in[4];
    const float* Wxf      = (const float*)d_in[5];
    const float* Whf      = (const float*)d_in[6];
    const float* bf       = (const float*)d_in[7];
    const float* Wxb      = (const float*)d_in[8];
    const float* Whb      = (const float*)d_in[9];
    const float* bb       = (const float*)d_in[10];
    const int*   training = (const int*)  d_in[11];
    float* out = (float*)d_out;

    const int GSMEM = 2 * STAGE + 256;
    cudaFuncSetAttribute(k_hgemm, cudaFuncAttributeMaxDynamicSharedMemorySize, GSMEM);

    k_init<<<512, 256>>>();
    k_stats<<<256, 512>>>(x);
    k_finalize<<<1, 512>>>(lengths, scale, bias, training);
    k_reorder<<<dim3(4096, 1, 4), 256>>>(Wxf, Whf, Wxb, Whb, bf, bb);
    k_bnapply<<<32768, 256>>>(x, mask, lengths);
    k_hgemm<<<dim3(16, 512, 2), 256, GSMEM>>>();
    k_lstm<<<128, 128>>>(out);
    k_combine<<<32768, 256>>>(out, lengths);
}

// round 5
// speedup vs baseline: 1.3645x; 1.3278x over previous
#include <cuda_runtime.h>
#include <cuda_bf16.h>
#include <cstdint>
#include <math.h>

#define TT    1024
#define BB    64
#define HH    512
#define HIDD  512
#define NG    2048           // 4*HID
#define NROWS 65536          // T*B

// ------------------------- scratch (static device memory; no allocs) -------------------------
// Z layout: [t][col(2048)][b(64)]  (transposed for contiguous per-block step slices)
static __device__ float d_Zf [(size_t)NROWS * NG];
static __device__ float d_Zb [(size_t)NROWS * NG];
static __device__ float d_bwd[(size_t)NROWS * HIDD];   // raw backward states [t*B+b][hid]
static __device__ unsigned short d_Yh [(size_t)NROWS * HH];
static __device__ unsigned short d_Yl [(size_t)NROWS * HH];
static __device__ unsigned short d_Yrh[(size_t)NROWS * HH];
static __device__ unsigned short d_Yrl[(size_t)NROWS * HH];
static __device__ unsigned short d_Wxh[2][NG * HH];    // [n'][k] gate-interleaved
static __device__ unsigned short d_Wxl[2][NG * HH];
static __device__ float d_Whr[2][HIDD * NG];           // [k][n'] gate-interleaved fp32
static __device__ float d_brd[2][NG];
static __device__ float d_hT [2][2][HIDD * BB];        // double-buffered h^T [hid][batch]
static __device__ float d_sum[HH];
static __device__ float d_sumsq[HH];
static __device__ float d_an[HH];
static __device__ float d_b2[HH];
static __device__ unsigned d_bar;

__device__ __forceinline__ float sigm(float x) { return 1.0f / (1.0f + __expf(-x)); }

__device__ __forceinline__ uint32_t smem_u32(const void* p) {
    uint32_t a;
    asm("{ .reg .u64 t; cvta.to.shared.u64 t, %1; cvt.u32.u64 %0, t; }" : "=r"(a) : "l"(p));
    return a;
}

__device__ __forceinline__ void cpa16(uint32_t dst, const void* src) {
    asm volatile("cp.async.cg.shared.global [%0], [%1], 16;" :: "r"(dst), "l"(src));
}
#define CPA_COMMIT() asm volatile("cp.async.commit_group;" ::: "memory")
#define CPA_WAIT1()  asm volatile("cp.async.wait_group 1;" ::: "memory")
#define CPA_WAIT0()  asm volatile("cp.async.wait_group 0;" ::: "memory")

__device__ __forceinline__ void ldsm4(uint32_t* d, uint32_t a) {
    asm volatile("ldmatrix.sync.aligned.m8n8.x4.shared.b16 {%0,%1,%2,%3}, [%4];"
                 : "=r"(d[0]), "=r"(d[1]), "=r"(d[2]), "=r"(d[3]) : "r"(a));
}
__device__ __forceinline__ void ldsm2(uint32_t* d, uint32_t a) {
    asm volatile("ldmatrix.sync.aligned.m8n8.x2.shared.b16 {%0,%1}, [%2];"
                 : "=r"(d[0]), "=r"(d[1]) : "r"(a));
}
__device__ __forceinline__ void mma16816(float* d, const uint32_t* a, const uint32_t* b) {
    asm volatile("mma.sync.aligned.m16n8k16.row.col.f32.bf16.bf16.f32 "
                 "{%0,%1,%2,%3}, {%4,%5,%6,%7}, {%8,%9}, {%0,%1,%2,%3};"
                 : "+f"(d[0]), "+f"(d[1]), "+f"(d[2]), "+f"(d[3])
                 : "r"(a[0]), "r"(a[1]), "r"(a[2]), "r"(a[3]), "r"(b[0]), "r"(b[1]));
}

__device__ __forceinline__ void mbar_init(uint32_t m) {
    asm volatile("mbarrier.init.shared.b64 [%0], 1;" :: "r"(m) : "memory");
}
__device__ __forceinline__ void mbar_expect(uint32_t m, uint32_t bytes) {
    asm volatile("mbarrier.arrive.expect_tx.shared.b64 _, [%0], %1;"
                 :: "r"(m), "r"(bytes) : "memory");
}
__device__ __forceinline__ void mbar_wait(uint32_t m, uint32_t ph) {
    asm volatile(
        "{\n\t.reg .pred P;\n\tLW%=:\n\t"
        "mbarrier.try_wait.parity.acquire.cta.shared::cta.b64 P, [%0], %1;\n\t"
        "@!P bra LW%=;\n\t}"
        :: "r"(m), "r"(ph) : "memory");
}
__device__ __forceinline__ void bulk_g2s(uint32_t dst, const void* src, uint32_t bytes,
                                         uint32_t mbar) {
    asm volatile(
        "cp.async.bulk.shared::cluster.global.mbarrier::complete_tx::bytes [%0], [%1], %2, [%3];"
        :: "r"(dst), "l"(src), "r"(bytes), "r"(mbar) : "memory");
}

// ------------------------- init -------------------------
__global__ void k_init() {
    int i = blockIdx.x * blockDim.x + threadIdx.x;
    if (i < 2 * 2 * HIDD * BB) ((float*)d_hT)[i] = 0.0f;
    if (i < HH) { d_sum[i] = 0.0f; d_sumsq[i] = 0.0f; }
    if (i == 0) d_bar = 0u;
}

// ------------------------- batchnorm column sums -------------------------
__global__ void k_stats(const float* __restrict__ x) {
    int c = threadIdx.x;
    size_t r0 = (size_t)blockIdx.x * 256;
    float s = 0.0f, s2 = 0.0f;
    for (int r = 0; r < 256; r++) {
        float v = x[(r0 + r) * (size_t)HH + c];
        s += v; s2 += v * v;
    }
    atomicAdd(&d_sum[c], s);
    atomicAdd(&d_sumsq[c], s2);
}

// ------------------------- finalize BN params -------------------------
__global__ void k_finalize(const int* __restrict__ lengths, const float* __restrict__ scale,
                           const float* __restrict__ bias, const int* __restrict__ training) {
    __shared__ float s_nz;
    int tid = threadIdx.x;
    if (tid == 0) {
        int s = 0;
        for (int b = 0; b < BB; b++) s += lengths[b];
        s_nz = (float)s;
    }
    __syncthreads();
    float mean, var;
    if (*training) {
        float nz = s_nz;
        mean = d_sum[tid] / nz;
        float m2 = d_sumsq[tid] / nz;
        var = fmaxf(0.0f, m2 - mean * mean);
    } else {
        mean = 0.0f; var = 1.0f;
    }
    float a = rsqrtf(var + 1e-5f) * scale[tid];
    d_an[tid] = a;
    d_b2[tid] = bias[tid] - mean * a;
}

// ------------------------- weight reorder -------------------------
__global__ void k_reorder(const float* __restrict__ Wxf, const float* __restrict__ Whf,
                          const float* __restrict__ Wxb, const float* __restrict__ Whb,
                          const float* __restrict__ bf,  const float* __restrict__ bb) {
    int z = blockIdx.z;
    int i = blockIdx.x * 256 + threadIdx.x;
    const float* src = (z == 0) ? Wxf : (z == 1) ? Whf : (z == 2) ? Wxb : Whb;
    if (z == 1 || z == 3) {
        int dir = z >> 1;
        int k = i >> 11, cn = i & 2047;
        int g = cn & 3, j = cn >> 2;
        d_Whr[dir][i] = src[(k << 11) + (g << 9) + j];
    } else {
        int dir = z >> 1;
        int k = i & 511, n = i >> 9;
        int g = n & 3, j = n >> 2;
        float v = src[(k << 11) + (g << 9) + j];
        __nv_bfloat16 h = __float2bfloat16_rn(v);
        float lo = v - __bfloat162float(h);
        d_Wxh[dir][i] = __bfloat16_as_ushort(h);
        d_Wxl[dir][i] = __bfloat16_as_ushort(__float2bfloat16_rn(lo));
        if (i < NG) {
            if (z == 0)      d_brd[0][i] = bf[((i & 3) << 9) + (i >> 2)];
            else             d_brd[1][i] = bb[((i & 3) << 9) + (i >> 2)];
        }
    }
}

// ------------------------- BN apply + mask + bf16 split + flip -------------------------
__global__ void k_bnapply(const float* __restrict__ x, const float* __restrict__ mask,
                          const int* __restrict__ lengths) {
    int i = blockIdx.x * 256 + threadIdx.x;
    int row = i >> 7;
    int c4  = (i & 127) << 2;
    int t = row >> 6, b = row & 63;
    float4 xv = *(const float4*)(x + ((size_t)row << 9) + c4);
    float4 av = *(const float4*)(d_an + c4);
    float4 bv = *(const float4*)(d_b2 + c4);
    float m = __ldg(mask + row);
    float y[4];
    y[0] = (xv.x * av.x + bv.x) * m;
    y[1] = (xv.y * av.y + bv.y) * m;
    y[2] = (xv.z * av.z + bv.z) * m;
    y[3] = (xv.w * av.w + bv.w) * m;
    uint2 hv, lv;
    unsigned hs[4], ls[4];
#pragma unroll
    for (int q = 0; q < 4; q++) {
        __nv_bfloat16 h = __float2bfloat16_rn(y[q]);
        float lo = y[q] - __bfloat162float(h);
        hs[q] = __bfloat16_as_ushort(h);
        ls[q] = __bfloat16_as_ushort(__float2bfloat16_rn(lo));
    }
    hv.x = hs[0] | (hs[1] << 16); hv.y = hs[2] | (hs[3] << 16);
    lv.x = ls[0] | (ls[1] << 16); lv.y = ls[2] | (ls[3] << 16);
    size_t o = ((size_t)row << 9) + c4;
    *(uint2*)(d_Yh + o) = hv;
    *(uint2*)(d_Yl + o) = lv;
    int l = __ldg(lengths + b);
    if (t < l) {
        size_t orr = ((size_t)((l - 1 - t) * BB + b) << 9) + c4;
        *(uint2*)(d_Yrh + orr) = hv;
        *(uint2*)(d_Yrl + orr) = lv;
    } else {
        *(uint2*)(d_Yrh + o) = make_uint2(0u, 0u);
        *(uint2*)(d_Yrl + o) = make_uint2(0u, 0u);
    }
}

// ------------------------- HMMA split-bf16 GEMM: Z = Y@Wx + b (transposed out) -------------
#define STAGE 32768
__global__ __launch_bounds__(256) void k_hgemm() {
    extern __shared__ char dsm[];
    uint32_t sb = (smem_u32(dsm) + 127) & ~127u;
    float* cs = (float*)(dsm + (sb - smem_u32(dsm)));
    int tid = threadIdx.x;
    int lane = tid & 31, wid = tid >> 5;
    int wm0 = (wid & 1) * 64;
    int wn0 = (wid >> 1) * 32;
    int n0 = blockIdx.x * 128;       // n fastest -> weight tiles L2 resident
    int m0 = blockIdx.y * 128;
    int dir = blockIdx.z;

    const unsigned short* Ah = (dir ? d_Yrh : d_Yh) + (size_t)m0 * 512;
    const unsigned short* Al = (dir ? d_Yrl : d_Yl) + (size_t)m0 * 512;
    const unsigned short* Bh = d_Wxh[dir] + (size_t)n0 * 512;
    const unsigned short* Bl = d_Wxl[dir] + (size_t)n0 * 512;

    float acc[4][4][4];
#pragma unroll
    for (int a = 0; a < 4; a++)
#pragma unroll
        for (int b = 0; b < 4; b++)
#pragma unroll
            for (int c = 0; c < 4; c++) acc[a][b][c] = 0.0f;

    auto load_chunk = [&](int s, int k0) {
        uint32_t bA = sb + s * STAGE, bB = bA + 16384;
#pragma unroll
        for (int it = 0; it < 4; it++) {
            int q = tid + it * 256;
            int r = q >> 3, c = q & 7;
            uint32_t sw = (uint32_t)r * 128 + (uint32_t)((c ^ (r & 7)) << 4);
            cpa16(bA + sw, (c < 4) ? (const void*)(Ah + (size_t)r * 512 + k0 + c * 8)
                                   : (const void*)(Al + (size_t)r * 512 + k0 + (c - 4) * 8));
            cpa16(bB + sw, (c < 4) ? (const void*)(Bh + (size_t)r * 512 + k0 + c * 8)
                                   : (const void*)(Bl + (size_t)r * 512 + k0 + (c - 4) * 8));
        }
    };

    load_chunk(0, 0);  CPA_COMMIT();
    load_chunk(1, 32); CPA_COMMIT();

    for (int i = 0; i < 16; i++) {
        if (i < 15) CPA_WAIT1(); else CPA_WAIT0();
        __syncthreads();
        uint32_t bA = sb + (i & 1) * STAGE, bB = bA + 16384;
#pragma unroll
        for (int ks = 0; ks < 2; ks++) {
            uint32_t ah[4][4], al[4][4];
#pragma unroll
            for (int mf = 0; mf < 4; mf++) {
                int r = wm0 + mf * 16 + (lane & 15);
                int ch = 2 * ks + (lane >> 4);
                ldsm4(ah[mf], bA + r * 128 + ((ch       ^ (r & 7)) << 4));
                ldsm4(al[mf], bA + r * 128 + (((ch + 4) ^ (r & 7)) << 4));
            }
#pragma unroll
            for (int nf = 0; nf < 4; nf++) {
                int rb = wn0 + nf * 8 + (lane & 7);
                int cb = 2 * ks + ((lane >> 3) & 1);
                uint32_t bh[2], bl[2];
                ldsm2(bh, bB + rb * 128 + ((cb       ^ (rb & 7)) << 4));
                ldsm2(bl, bB + rb * 128 + (((cb + 4) ^ (rb & 7)) << 4));
#pragma unroll
                for (int mf = 0; mf < 4; mf++) {
                    mma16816(acc[mf][nf], ah[mf], bh);
                    mma16816(acc[mf][nf], ah[mf], bl);
                    mma16816(acc[mf][nf], al[mf], bh);
                }
            }
        }
        __syncthreads();
        if (i + 2 < 16) { load_chunk(i & 1, (i + 2) * 32); CPA_COMMIT(); }
    }

    // stage into smem [128 rows][129] with bias
    const float* bias = d_brd[dir];
#pragma unroll
    for (int nf = 0; nf < 4; nf++) {
        int gc = wn0 + nf * 8 + (lane & 3) * 2;
        float b0 = __ldg(bias + n0 + gc), b1 = __ldg(bias + n0 + gc + 1);
#pragma unroll
        for (int mf = 0; mf < 4; mf++) {
            int r = wm0 + mf * 16 + (lane >> 2);
            cs[r * 129 + gc]             = acc[mf][nf][0] + b0;
            cs[r * 129 + gc + 1]         = acc[mf][nf][1] + b1;
            cs[(r + 8) * 129 + gc]       = acc[mf][nf][2] + b0;
            cs[(r + 8) * 129 + gc + 1]   = acc[mf][nf][3] + b1;
        }
    }
    __syncthreads();

    // write transposed: Z[t][col][b]
    float* Z = dir ? d_Zb : d_Zf;
    int t0 = m0 >> 6;
#pragma unroll
    for (int p = 0; p < 16; p++) {
        int q = tid + p * 256;                 // 4096 float4 writes
        int b4  = (q & 15) << 2;
        int col = (q >> 4) & 127;
        int th  = q >> 11;
        float4 v;
        v.x = cs[(th * 64 + b4 + 0) * 129 + col];
        v.y = cs[(th * 64 + b4 + 1) * 129 + col];
        v.z = cs[(th * 64 + b4 + 2) * 129 + col];
        v.w = cs[(th * 64 + b4 + 3) * 129 + col];
        *(float4*)(Z + ((size_t)(t0 + th) * NG + n0 + col) * BB + b4) = v;
    }
}

// ------------------------- persistent bidirectional LSTM recurrence v2 -------------------------
// 128 blocks (64/dir) x 256 threads. Wh slice resident in smem; h broadcast via 4x32KB
// cp.async.bulk per step; z slice (8KB) bulk-prefetched one step ahead.
#define LSMEM (65536 + 131072 + 16384 + 64)
__global__ __launch_bounds__(256) void k_lstm(float* __restrict__ out) {
    extern __shared__ char sm[];
    float* wsm = (float*)sm;                         // [512][32]   64KB
    float* hsm = (float*)(sm + 65536);               // [512][64]  128KB
    float* zsm = (float*)(sm + 65536 + 131072);      // [2][32][64] 16KB
    uint32_t mb = smem_u32(sm) + 65536 + 131072 + 16384;  // mbarriers

    int blk = blockIdx.x;
    int dir = blk >> 6;
    int n   = blk & 63;
    const float* __restrict__ Zx = dir ? d_Zb : d_Zf;
    float* __restrict__ hob = dir ? d_bwd : out;
    float* hbuf0 = d_hT[dir][0];
    float* hbuf1 = d_hT[dir][1];

    int tid = threadIdx.x;
    int tx = tid & 7;          // local hid
    int ty = tid >> 3;         // 0..31 -> rows 2ty, 2ty+1
    int j = n * 8 + tx;

    // load Wh slice [512 k][32 cols] once
    {
        const float* Wh = d_Whr[dir] + n * 32;
        for (int i = tid; i < 512 * 8; i += 256) {
            int k = i >> 3, c4 = (i & 7) << 2;
            *(float4*)(wsm + k * 32 + c4) = *(const float4*)(Wh + (size_t)k * NG + c4);
        }
    }
    if (tid == 0) {
#pragma unroll
        for (int c = 0; c < 6; c++) mbar_init(mb + c * 8);
    }
    __syncthreads();

    // prefetch z(0)
    if (tid == 0) {
        mbar_expect(mb + 32, 8192);
        bulk_g2s(smem_u32(zsm), Zx + (size_t)(0 * NG + n * 32) * BB, 8192, mb + 32);
    }

    unsigned long long a00, a01, a10, a11;
    float cst0 = 0.0f, cst1 = 0.0f;

    for (int t = 0; t < TT; t++) {
        const float* hcur = (t & 1) ? hbuf1 : hbuf0;
        float*       hnxt = (t & 1) ? hbuf0 : hbuf1;

        if (tid == 0) {
#pragma unroll
            for (int c = 0; c < 4; c++) {
                mbar_expect(mb + c * 8, 32768);
                bulk_g2s(smem_u32(hsm) + c * 32768, hcur + c * 8192, 32768, mb + c * 8);
            }
            if (t + 1 < TT) {
                int s = (t + 1) & 1;
                mbar_expect(mb + 32 + s * 8, 8192);
                bulk_g2s(smem_u32(zsm) + s * 8192,
                         Zx + ((size_t)(t + 1) * NG + n * 32) * BB, 8192, mb + 32 + s * 8);
            }
        }

        asm("mov.b64 %0, 0;" : "=l"(a00));
        asm("mov.b64 %0, 0;" : "=l"(a01));
        asm("mov.b64 %0, 0;" : "=l"(a10));
        asm("mov.b64 %0, 0;" : "=l"(a11));

#pragma unroll
        for (int c = 0; c < 4; c++) {
            mbar_wait(mb + c * 8, (uint32_t)(t & 1));
            const float* hp = hsm + c * 128 * 64 + ty * 2;
            const float* wp = wsm + c * 128 * 32 + tx * 4;
#pragma unroll 8
            for (int kk = 0; kk < 128; kk++) {
                float2 h2 = *(const float2*)(hp + kk * 64);
                ulonglong2 w2 = *(const ulonglong2*)(wp + kk * 32);
                unsigned long long hb0, hb1;
                asm("mov.b64 %0, {%1,%1};" : "=l"(hb0) : "r"(__float_as_uint(h2.x)));
                asm("mov.b64 %0, {%1,%1};" : "=l"(hb1) : "r"(__float_as_uint(h2.y)));
                asm("fma.rn.f32x2 %0, %1, %2, %0;" : "+l"(a00) : "l"(hb0), "l"(w2.x));
                asm("fma.rn.f32x2 %0, %1, %2, %0;" : "+l"(a01) : "l"(hb0), "l"(w2.y));
                asm("fma.rn.f32x2 %0, %1, %2, %0;" : "+l"(a10) : "l"(hb1), "l"(w2.x));
                asm("fma.rn.f32x2 %0, %1, %2, %0;" : "+l"(a11) : "l"(hb1), "l"(w2.y));
            }
        }

        // z for this step
        mbar_wait(mb + 32 + (t & 1) * 8, (uint32_t)((t >> 1) & 1));
        const float* zb = zsm + (t & 1) * 2048;
        int r0 = ty * 2;
        uint32_t u0, u1, u2, u3;
        float hn0, hn1;
        {
            asm("mov.b64 {%0,%1}, %2;" : "=r"(u0), "=r"(u1) : "l"(a00));
            asm("mov.b64 {%0,%1}, %2;" : "=r"(u2), "=r"(u3) : "l"(a01));
            float zi = __uint_as_float(u0) + zb[(tx * 4 + 0) * 64 + r0];
            float zf = __uint_as_float(u1) + zb[(tx * 4 + 1) * 64 + r0];
            float zg = __uint_as_float(u2) + zb[(tx * 4 + 2) * 64 + r0];
            float zo = __uint_as_float(u3) + zb[(tx * 4 + 3) * 64 + r0];
            float cn = sigm(zf) * cst0 + sigm(zi) * tanhf(zg);
            cst0 = cn;
            hn0 = sigm(zo) * tanhf(cn);
        }
        {
            asm("mov.b64 {%0,%1}, %2;" : "=r"(u0), "=r"(u1) : "l"(a10));
            asm("mov.b64 {%0,%1}, %2;" : "=r"(u2), "=r"(u3) : "l"(a11));
            float zi = __uint_as_float(u0) + zb[(tx * 4 + 0) * 64 + r0 + 1];
            float zf = __uint_as_float(u1) + zb[(tx * 4 + 1) * 64 + r0 + 1];
            float zg = __uint_as_float(u2) + zb[(tx * 4 + 2) * 64 + r0 + 1];
            float zo = __uint_as_float(u3) + zb[(tx * 4 + 3) * 64 + r0 + 1];
            float cn = sigm(zf) * cst1 + sigm(zi) * tanhf(zg);
            cst1 = cn;
            hn1 = sigm(zo) * tanhf(cn);
        }

        // publish h(t+1) and outputs
        *(float2*)(hnxt + j * BB + r0) = make_float2(hn0, hn1);
        hob[((size_t)(t * BB + r0)) * HIDD + j]     = hn0;
        hob[((size_t)(t * BB + r0 + 1)) * HIDD + j] = hn1;

        // grid barrier
        __threadfence();
        __syncthreads();
        if (tid == 0) {
            atomicAdd(&d_bar, 1u);
            unsigned target = (unsigned)(t + 1) * gridDim.x;
            volatile unsigned* vb = &d_bar;
            while (*vb < target) { }
            __threadfence();
        }
        __syncthreads();
    }
}

// ------------------------- combine: out += flip(bwd) -------------------------
__global__ void k_combine(float* __restrict__ out, const int* __restrict__ lengths) {
    int i = blockIdx.x * 256 + threadIdx.x;
    int row = i >> 7;
    int c4  = (i & 127) << 2;
    int t = row >> 6, b = row & 63;
    int l = __ldg(lengths + b);
    int src = (t < l) ? (l - 1 - t) : (TT - 1 - t + l);
    float4 v = *(const float4*)(d_bwd + ((size_t)(src * BB + b) << 9) + c4);
    float4* po = (float4*)(out + ((size_t)row << 9) + c4);
    float4 o = *po;
    o.x += v.x; o.y += v.y; o.z += v.z; o.w += v.w;
    *po = o;
}

// ------------------------- launch -------------------------
extern "C" void kernel_launch(void* const* d_in, const int* in_sizes, int n_in,
                              void* d_out, int out_size) {
    const float* x        = (const float*)d_in[0];
    const int*   lengths  = (const int*)  d_in[1];
    const float* mask     = (const float*)d_in[2];
    const float* scale    = (const float*)d_in[3];
    const float* bias     = (const float*)d_in[4];
    const float* Wxf      = (const float*)d_in[5];
    const float* Whf      = (const float*)d_in[6];
    const float* bf       = (const float*)d_in[7];
    const float* Wxb      = (const float*)d_in[8];
    const float* Whb      = (const float*)d_in[9];
    const float* bb       = (const float*)d_in[10];
    const int*   training = (const int*)  d_in[11];
    float* out = (float*)d_out;

    const int GSMEM = 128 * 129 * 4 + 256;            // epilogue staging (covers 2*STAGE)
    cudaFuncSetAttribute(k_hgemm, cudaFuncAttributeMaxDynamicSharedMemorySize, GSMEM);
    cudaFuncSetAttribute(k_lstm, cudaFuncAttributeMaxDynamicSharedMemorySize, LSMEM);

    k_init<<<512, 256>>>();
    k_stats<<<256, 512>>>(x);
    k_finalize<<<1, 512>>>(lengths, scale, bias, training);
    k_reorder<<<dim3(4096, 1, 4), 256>>>(Wxf, Whf, Wxb, Whb, bf, bb);
    k_bnapply<<<32768, 256>>>(x, mask, lengths);
    k_hgemm<<<dim3(16, 512, 2), 256, GSMEM>>>();
    k_lstm<<<128, 256, LSMEM>>>(out);
    k_combine<<<32768, 256>>>(out, lengths);
}